// round 11
// baseline (speedup 1.0000x reference)
#include <cuda_runtime.h>
#include <cstddef>

#define NS   8192
#define NKK  8192
#define HID  1024
#define SENTD 1024
#define D2   2048

// ---------------- scratch (no allocation allowed) ----------------
__device__ float g_S[(size_t)NS * HID];     // 32 MB
__device__ float g_K[(size_t)NKK * HID];    // 32 MB
__device__ float g_pbuf[32 * NKK];          // partial max / partial sum
__device__ float g_cmax[NKK];
__device__ float g_crcp[NKK];

// ---------------- tiled fp32 GEMM ----------------
// C[M,N] = A[M,Kd] * op(B) (+ bias[n])
//   B_NK = true : B is [N,Kd] row-major (NT gemm: C = A * B^T)
//   B_NK = false: B is [Kd,N] row-major (NN gemm: C = A * B)
// BM=BN=128, BK=16, 256 threads, 8x8 per-thread tile. All dims divide tiles.
template<bool B_NK>
__global__ __launch_bounds__(256)
void sgemm128(const float* __restrict__ A, const float* __restrict__ B,
              const float* __restrict__ bias, float* __restrict__ C,
              int M, int N, int Kd)
{
    constexpr int BM = 128, BN = 128, BK = 16, TM = 8, TN = 8;
    __shared__ float As[BK][BM];
    __shared__ float Bs[BK][BN];

    const int tid = threadIdx.x;
    const int bm  = blockIdx.y * BM;
    const int bn  = blockIdx.x * BN;
    const int tx  = tid & 15;    // 16 thread-cols
    const int ty  = tid >> 4;    // 16 thread-rows

    // loader mapping for [rows=128, cols=BK] K-major tiles (A, and B when B_NK)
    const int lrow = tid >> 2;          // 0..63 (+64)
    const int lcol = (tid & 3) * 4;     // 0,4,8,12
    // loader mapping for [rows=BK, cols=128] N-major tiles (B when !B_NK)
    const int brow = tid >> 5;          // 0..7 (+8)
    const int bcol = (tid & 31) * 4;    // 0..124

    float acc[TM][TN];
#pragma unroll
    for (int i = 0; i < TM; i++)
#pragma unroll
        for (int j = 0; j < TN; j++) acc[i][j] = 0.0f;

    for (int k0 = 0; k0 < Kd; k0 += BK) {
        // --- load A tile (transpose into As[k][m]) ---
#pragma unroll
        for (int i = 0; i < 2; i++) {
            int r = lrow + i * 64;
            float4 v = *reinterpret_cast<const float4*>(
                &A[(size_t)(bm + r) * Kd + k0 + lcol]);
            As[lcol + 0][r] = v.x;
            As[lcol + 1][r] = v.y;
            As[lcol + 2][r] = v.z;
            As[lcol + 3][r] = v.w;
        }
        // --- load B tile ---
        if (B_NK) {
#pragma unroll
            for (int i = 0; i < 2; i++) {
                int r = lrow + i * 64;
                float4 v = *reinterpret_cast<const float4*>(
                    &B[(size_t)(bn + r) * Kd + k0 + lcol]);
                Bs[lcol + 0][r] = v.x;
                Bs[lcol + 1][r] = v.y;
                Bs[lcol + 2][r] = v.z;
                Bs[lcol + 3][r] = v.w;
            }
        } else {
#pragma unroll
            for (int i = 0; i < 2; i++) {
                int r = brow + i * 8;
                float4 v = *reinterpret_cast<const float4*>(
                    &B[(size_t)(k0 + r) * N + bn + bcol]);
                *reinterpret_cast<float4*>(&Bs[r][bcol]) = v;
            }
        }
        __syncthreads();

#pragma unroll
        for (int k = 0; k < BK; k++) {
            float ar[TM], br[TN];
            *reinterpret_cast<float4*>(&ar[0]) =
                *reinterpret_cast<const float4*>(&As[k][ty * TM]);
            *reinterpret_cast<float4*>(&ar[4]) =
                *reinterpret_cast<const float4*>(&As[k][ty * TM + 4]);
            *reinterpret_cast<float4*>(&br[0]) =
                *reinterpret_cast<const float4*>(&Bs[k][tx * TN]);
            *reinterpret_cast<float4*>(&br[4]) =
                *reinterpret_cast<const float4*>(&Bs[k][tx * TN + 4]);
#pragma unroll
            for (int i = 0; i < TM; i++)
#pragma unroll
                for (int j = 0; j < TN; j++)
                    acc[i][j] = fmaf(ar[i], br[j], acc[i][j]);
        }
        __syncthreads();
    }

    // --- epilogue ---
#pragma unroll
    for (int i = 0; i < TM; i++) {
        const int row = bm + ty * TM + i;
#pragma unroll
        for (int j = 0; j < TN; j += 4) {
            const int col = bn + tx * TN + j;
            float4 v;
            v.x = acc[i][j + 0];
            v.y = acc[i][j + 1];
            v.z = acc[i][j + 2];
            v.w = acc[i][j + 3];
            if (bias != nullptr) {
                v.x += bias[col + 0];
                v.y += bias[col + 1];
                v.z += bias[col + 2];
                v.w += bias[col + 3];
            }
            *reinterpret_cast<float4*>(&C[(size_t)row * N + col]) = v;
        }
    }
}

// ---------------- column softmax (axis=0) on row-major [NS, NKK] ----------------
// pass 1a: partial max over 256-row chunks (coalesced: thread = column)
__global__ void col_pmax(const float* __restrict__ scores, float* __restrict__ pmax)
{
    const int col = blockIdx.x * blockDim.x + threadIdx.x;  // 8192 cols
    const int r0  = blockIdx.y * 256;
    float m = -3.4e38f;
#pragma unroll 16
    for (int r = 0; r < 256; r++)
        m = fmaxf(m, scores[(size_t)(r0 + r) * NKK + col]);
    pmax[blockIdx.y * NKK + col] = m;
}

__global__ void col_max_reduce(const float* __restrict__ pmax, float* __restrict__ cmax)
{
    const int col = blockIdx.x * blockDim.x + threadIdx.x;
    float m = -3.4e38f;
#pragma unroll
    for (int rc = 0; rc < 32; rc++) m = fmaxf(m, pmax[rc * NKK + col]);
    cmax[col] = m;
}

// pass 1b: partial sum of exp (reads scores again; no write of exp)
__global__ void col_psum(const float* __restrict__ scores,
                         const float* __restrict__ cmax,
                         float* __restrict__ psum)
{
    const int col = blockIdx.x * blockDim.x + threadIdx.x;
    const int r0  = blockIdx.y * 256;
    const float mx = cmax[col];
    float s = 0.0f;
#pragma unroll 16
    for (int r = 0; r < 256; r++)
        s += __expf(scores[(size_t)(r0 + r) * NKK + col] - mx);
    psum[blockIdx.y * NKK + col] = s;
}

__global__ void col_sum_reduce(const float* __restrict__ psum, float* __restrict__ crcp)
{
    const int col = blockIdx.x * blockDim.x + threadIdx.x;
    float s = 0.0f;
#pragma unroll
    for (int rc = 0; rc < 32; rc++) s += psum[rc * NKK + col];
    crcp[col] = 1.0f / s;
}

// pass 2: attns = exp(score - max) * rcp, in place
__global__ void softmax_write(float* __restrict__ attns,
                              const float* __restrict__ cmax,
                              const float* __restrict__ crcp)
{
    const int col = blockIdx.x * blockDim.x + threadIdx.x;
    const int r0  = blockIdx.y * 32;
    const float mx = cmax[col];
    const float rc = crcp[col];
#pragma unroll
    for (int r = 0; r < 32; r++) {
        const size_t idx = (size_t)(r0 + r) * NKK + col;
        attns[idx] = __expf(attns[idx] - mx) * rc;
    }
}

// ---------------- launch ----------------
extern "C" void kernel_launch(void* const* d_in, const int* in_sizes, int n_in,
                              void* d_out, int out_size)
{
    (void)in_sizes; (void)n_in; (void)out_size;
    const float* sent  = (const float*)d_in[0];   // [8192, 1024]
    const float* knowl = (const float*)d_in[1];   // [8192, 2048]
    const float* Ws    = (const float*)d_in[2];   // [1024, 1024]
    const float* bs    = (const float*)d_in[3];   // [1024]
    const float* Wk    = (const float*)d_in[4];   // [1024, 2048]
    const float* bk    = (const float*)d_in[5];   // [1024]

    float* attns = (float*)d_out;                       // [8192, 8192]
    float* fused = attns + (size_t)NS * NKK;            // [8192, 2048]

    float *Sbuf, *Kbuf, *pbuf, *cmaxp, *crcpp;
    cudaGetSymbolAddress((void**)&Sbuf,  g_S);
    cudaGetSymbolAddress((void**)&Kbuf,  g_K);
    cudaGetSymbolAddress((void**)&pbuf,  g_pbuf);
    cudaGetSymbolAddress((void**)&cmaxp, g_cmax);
    cudaGetSymbolAddress((void**)&crcpp, g_crcp);

    // 1) S = sent @ Ws^T + bs   [8192, 1024]
    sgemm128<true><<<dim3(HID / 128, NS / 128), 256>>>(
        sent, Ws, bs, Sbuf, NS, HID, SENTD);

    // 2) K = knowl @ Wk^T + bk  [8192, 1024]
    sgemm128<true><<<dim3(HID / 128, NKK / 128), 256>>>(
        knowl, Wk, bk, Kbuf, NKK, HID, 2 * HID);

    // 3) scores = S @ K^T       [8192, 8192] -> attns region
    sgemm128<true><<<dim3(NKK / 128, NS / 128), 256>>>(
        Sbuf, Kbuf, nullptr, attns, NS, NKK, HID);

    // 4) column softmax (axis=0)
    col_pmax      <<<dim3(NKK / 256, 32), 256>>>(attns, pbuf);
    col_max_reduce<<<NKK / 256, 256>>>(pbuf, cmaxp);
    col_psum      <<<dim3(NKK / 256, 32), 256>>>(attns, cmaxp, pbuf);
    col_sum_reduce<<<NKK / 256, 256>>>(pbuf, crcpp);
    softmax_write <<<dim3(NKK / 256, NS / 32), 256>>>(attns, cmaxp, crcpp);

    // 5) fused = attns @ V      [8192, 2048]  (V = knowledge_embedding, NN gemm)
    sgemm128<false><<<dim3(D2 / 128, NS / 128), 256>>>(
        attns, knowl, nullptr, fused, NS, D2, NKK);
}

// round 15
// speedup vs baseline: 3.0918x; 3.0918x over previous
#include <cuda_runtime.h>
#include <cuda_bf16.h>
#include <cstdint>
#include <cstddef>

#define NS   8192
#define NKK  8192
#define HID  1024
#define D2   2048

// ---------------- scratch (module globals; no runtime allocation) ----------------
__device__ __align__(1024) __nv_bfloat16 g_sh[(size_t)NS * HID];
__device__ __align__(1024) __nv_bfloat16 g_sl[(size_t)NS * HID];
__device__ __align__(1024) __nv_bfloat16 g_wsh[(size_t)HID * HID];
__device__ __align__(1024) __nv_bfloat16 g_wsl[(size_t)HID * HID];
__device__ __align__(1024) __nv_bfloat16 g_wkh[(size_t)HID * D2];
__device__ __align__(1024) __nv_bfloat16 g_wkl[(size_t)HID * D2];
__device__ __align__(1024) __nv_bfloat16 g_knh[(size_t)NKK * D2];
__device__ __align__(1024) __nv_bfloat16 g_knl[(size_t)NKK * D2];
__device__ __align__(1024) __nv_bfloat16 g_vh[(size_t)D2 * NKK];
__device__ __align__(1024) __nv_bfloat16 g_vl[(size_t)D2 * NKK];
__device__ __align__(1024) __nv_bfloat16 g_Sh[(size_t)NS * HID];
__device__ __align__(1024) __nv_bfloat16 g_Sl[(size_t)NS * HID];
__device__ __align__(1024) __nv_bfloat16 g_Kh[(size_t)NKK * HID];
__device__ __align__(1024) __nv_bfloat16 g_Kl[(size_t)NKK * HID];
__device__ __align__(1024) __nv_bfloat16 g_Ah[(size_t)NS * NKK];
__device__ __align__(1024) __nv_bfloat16 g_Al[(size_t)NS * NKK];
__device__ float g_pbuf[32 * NKK];
__device__ float g_cmax[NKK];
__device__ float g_crcp[NKK];

// ---------------- low-level helpers (sm_80-era PTX only: safe on compute_103) ----
__device__ __forceinline__ uint32_t s2u(const void* p) {
    uint32_t a;
    asm("{ .reg .u64 t; cvta.to.shared.u64 t, %1; cvt.u32.u64 %0, t; }"
        : "=r"(a) : "l"(p));
    return a;
}

__device__ __forceinline__ void ldsm4(uint32_t* r, uint32_t addr) {
    asm volatile("ldmatrix.sync.aligned.m8n8.x4.shared.b16 {%0,%1,%2,%3}, [%4];"
                 : "=r"(r[0]), "=r"(r[1]), "=r"(r[2]), "=r"(r[3]) : "r"(addr));
}

__device__ __forceinline__ void mma16816(float* c, const uint32_t* a, const uint32_t* b) {
    asm volatile(
        "mma.sync.aligned.m16n8k16.row.col.f32.bf16.bf16.f32 "
        "{%0,%1,%2,%3}, {%4,%5,%6,%7}, {%8,%9}, {%0,%1,%2,%3};"
        : "+f"(c[0]), "+f"(c[1]), "+f"(c[2]), "+f"(c[3])
        : "r"(a[0]), "r"(a[1]), "r"(a[2]), "r"(a[3]), "r"(b[0]), "r"(b[1]));
}

// SW128 swizzle of a (row*128 + kb) byte offset within a 128B-row tile.
// For kb < 128: sw = row*128 + (kb ^ ((row&7)<<4)).
__device__ __forceinline__ uint32_t swz(int row, int kb) {
    return (uint32_t)(row * 128 + (kb ^ ((row & 7) << 4)));
}

static constexpr int TILE = 16384;                    // 128 rows x 128 bytes
static constexpr int SMEM_MMA = 2 * 4 * TILE;         // 2 stages x 4 half-tiles = 128KB

// load one 128-row x 64-bf16 (128B/row) K-major tile via cp.async, SW128 swizzle.
// 256 threads, 1024 16B-chunks -> 4 iterations.
__device__ __forceinline__ void load_half_tile(uint32_t sdst,
                                               const __nv_bfloat16* __restrict__ g,
                                               int ld, int row0, int k0, int tid) {
#pragma unroll
    for (int i = 0; i < 4; i++) {
        const int idx = i * 256 + tid;        // 0..1023
        const int row = idx >> 3;             // 0..127
        const int kb  = (idx & 7) * 16;       // 0..112 bytes
        const __nv_bfloat16* gp = g + (size_t)(row0 + row) * ld + k0 + (kb >> 1);
        asm volatile("cp.async.cg.shared.global [%0], [%1], 16;\n"
                     :: "r"(sdst + swz(row, kb)), "l"(gp));
    }
}

// ---------------- split-bf16 HMMA NT GEMM ----------------
// C[M,N] = (Ah+Al)[M,Kd] @ (Bh+Bl)[N,Kd]^T (+bias).
// SPLIT_OUT: emit bf16 hi/lo pair (Ch, Cl) instead of fp32 C.
template<bool SPLIT_OUT>
__global__ __launch_bounds__(256, 1)
void mma_nt(const __nv_bfloat16* __restrict__ Ahp, const __nv_bfloat16* __restrict__ Alp,
            const __nv_bfloat16* __restrict__ Bhp, const __nv_bfloat16* __restrict__ Blp,
            const float* __restrict__ bias, float* __restrict__ C,
            __nv_bfloat16* __restrict__ Ch, __nv_bfloat16* __restrict__ Cl,
            int N, int Kd)
{
    extern __shared__ char smem[];
    const int tid  = threadIdx.x;
    const int wid  = tid >> 5;
    const int lane = tid & 31;
    const int bm = blockIdx.y * 128, bn = blockIdx.x * 128;

    // warp grid: 2 (m) x 4 (n); warp tile 64 (m) x 32 (n)
    const int wm0 = (wid & 1) * 64;
    const int wn0 = (wid >> 1) * 32;

    const uint32_t sb  = s2u(smem);
    const uint32_t st[2] = { sb, sb + 4 * TILE };

    float acc[4][4][4];
#pragma unroll
    for (int i = 0; i < 4; i++)
#pragma unroll
        for (int j = 0; j < 4; j++)
#pragma unroll
            for (int q = 0; q < 4; q++) acc[i][j][q] = 0.0f;

    // per-thread ldmatrix address components (row-dependent parts)
    // A: row = wm0 + mi*16 + (lane&15); k-halve select = lane>>4
    uint32_t aOff[4];
#pragma unroll
    for (int mi = 0; mi < 4; mi++) {
        const int r = wm0 + mi * 16 + (lane & 15);
        aOff[mi] = (uint32_t)(r * 128) ;
    }
    const uint32_t aXor = (uint32_t)(((wm0 + (lane & 15)) & 7) << 4);
    const int aKhb = (lane >> 4) * 16;       // 0 or 16 bytes
    // B: row = wn0 + npair*16 + ((lane>>4)&1)*8 + (lane&7); k-halve = (lane>>3)&1
    uint32_t bOff[2];
    const int bRowBase = wn0 + ((lane >> 4) & 1) * 8 + (lane & 7);
#pragma unroll
    for (int p = 0; p < 2; p++)
        bOff[p] = (uint32_t)((bRowBase + p * 16) * 128);
    const uint32_t bXor = (uint32_t)((bRowBase & 7) << 4);
    const int bKhb = ((lane >> 3) & 1) * 16;

    const int NC = Kd >> 6;   // 64-wide K chunks

    // prologue: stage 0 (chunk 0), stage 1 (chunk 1)
    load_half_tile(st[0],            Ahp, Kd, bm, 0, tid);
    load_half_tile(st[0] + TILE,     Alp, Kd, bm, 0, tid);
    load_half_tile(st[0] + 2 * TILE, Bhp, Kd, bn, 0, tid);
    load_half_tile(st[0] + 3 * TILE, Blp, Kd, bn, 0, tid);
    asm volatile("cp.async.commit_group;" ::: "memory");
    if (NC > 1) {
        load_half_tile(st[1],            Ahp, Kd, bm, 64, tid);
        load_half_tile(st[1] + TILE,     Alp, Kd, bm, 64, tid);
        load_half_tile(st[1] + 2 * TILE, Bhp, Kd, bn, 64, tid);
        load_half_tile(st[1] + 3 * TILE, Blp, Kd, bn, 64, tid);
        asm volatile("cp.async.commit_group;" ::: "memory");
    }

    for (int c = 0; c < NC; c++) {
        if (c + 1 < NC) { asm volatile("cp.async.wait_group 1;" ::: "memory"); }
        else            { asm volatile("cp.async.wait_group 0;" ::: "memory"); }
        __syncthreads();

        const uint32_t base = st[c & 1];
#pragma unroll
        for (int ks = 0; ks < 4; ks++) {
            const int kb = ks * 32;
            uint32_t ah[4][4], al[4][4], bh[2][4], bl[2][4];
#pragma unroll
            for (int mi = 0; mi < 4; mi++) {
                const uint32_t ad = base + aOff[mi] + (uint32_t)((kb + aKhb) ^ aXor);
                ldsm4(ah[mi], ad);
                ldsm4(al[mi], ad + TILE);
            }
#pragma unroll
            for (int p = 0; p < 2; p++) {
                const uint32_t bd = base + 2 * TILE + bOff[p] + (uint32_t)((kb + bKhb) ^ bXor);
                ldsm4(bh[p], bd);
                ldsm4(bl[p], bd + TILE);
            }
#pragma unroll
            for (int mi = 0; mi < 4; mi++)
#pragma unroll
                for (int ni = 0; ni < 4; ni++) {
                    const uint32_t* bhp = &bh[ni >> 1][(ni & 1) * 2];
                    const uint32_t* blp = &bl[ni >> 1][(ni & 1) * 2];
                    mma16816(acc[mi][ni], ah[mi], bhp);
                    mma16816(acc[mi][ni], ah[mi], blp);
                    mma16816(acc[mi][ni], al[mi], bhp);
                }
        }
        __syncthreads();

        if (c + 2 < NC) {
            const uint32_t b2 = st[c & 1];
            const int k0 = (c + 2) << 6;
            load_half_tile(b2,            Ahp, Kd, bm, k0, tid);
            load_half_tile(b2 + TILE,     Alp, Kd, bm, k0, tid);
            load_half_tile(b2 + 2 * TILE, Bhp, Kd, bn, k0, tid);
            load_half_tile(b2 + 3 * TILE, Blp, Kd, bn, k0, tid);
            asm volatile("cp.async.commit_group;" ::: "memory");
        }
    }

    // ---------------- epilogue ----------------
    const bool hb = (bias != nullptr);
#pragma unroll
    for (int mi = 0; mi < 4; mi++) {
#pragma unroll
        for (int half = 0; half < 2; half++) {
            const int row = bm + wm0 + mi * 16 + (lane >> 2) + half * 8;
#pragma unroll
            for (int ni = 0; ni < 4; ni++) {
                const int col = bn + wn0 + ni * 8 + (lane & 3) * 2;
                float v0 = acc[mi][ni][half * 2 + 0];
                float v1 = acc[mi][ni][half * 2 + 1];
                if (hb) { v0 += bias[col]; v1 += bias[col + 1]; }
                const size_t idx = (size_t)row * N + col;
                if (SPLIT_OUT) {
                    __nv_bfloat16 h0 = __float2bfloat16(v0);
                    __nv_bfloat16 h1 = __float2bfloat16(v1);
                    __nv_bfloat16 l0 = __float2bfloat16(v0 - __bfloat162float(h0));
                    __nv_bfloat16 l1 = __float2bfloat16(v1 - __bfloat162float(h1));
                    *reinterpret_cast<__nv_bfloat162*>(Ch + idx) = __halves2bfloat162(h0, h1);
                    *reinterpret_cast<__nv_bfloat162*>(Cl + idx) = __halves2bfloat162(l0, l1);
                } else {
                    float2 v; v.x = v0; v.y = v1;
                    *reinterpret_cast<float2*>(C + idx) = v;
                }
            }
        }
    }
}

// ---------------- fp32 -> bf16 hi/lo split (elementwise) ----------------
__global__ void split2(const float* __restrict__ x, __nv_bfloat16* __restrict__ h,
                       __nv_bfloat16* __restrict__ l, size_t n)
{
    const size_t stride = (size_t)gridDim.x * blockDim.x * 4;
    for (size_t j = ((size_t)blockIdx.x * blockDim.x + threadIdx.x) * 4; j < n; j += stride) {
        float4 v = *reinterpret_cast<const float4*>(x + j);
        __nv_bfloat16 h0 = __float2bfloat16(v.x), h1 = __float2bfloat16(v.y);
        __nv_bfloat16 h2 = __float2bfloat16(v.z), h3 = __float2bfloat16(v.w);
        __nv_bfloat16 l0 = __float2bfloat16(v.x - __bfloat162float(h0));
        __nv_bfloat16 l1 = __float2bfloat16(v.y - __bfloat162float(h1));
        __nv_bfloat16 l2 = __float2bfloat16(v.z - __bfloat162float(h2));
        __nv_bfloat16 l3 = __float2bfloat16(v.w - __bfloat162float(h3));
        *reinterpret_cast<__nv_bfloat162*>(h + j)     = __halves2bfloat162(h0, h1);
        *reinterpret_cast<__nv_bfloat162*>(h + j + 2) = __halves2bfloat162(h2, h3);
        *reinterpret_cast<__nv_bfloat162*>(l + j)     = __halves2bfloat162(l0, l1);
        *reinterpret_cast<__nv_bfloat162*>(l + j + 2) = __halves2bfloat162(l2, l3);
    }
}

// ---------------- transpose + split: knowl [R,Cc] -> vh/vl [Cc,R] ----------------
__global__ void tsplit(const float* __restrict__ in, __nv_bfloat16* __restrict__ oh,
                       __nv_bfloat16* __restrict__ ol, int R, int Cc)
{
    __shared__ float t[32][33];
    const int c0 = blockIdx.x * 32, r0 = blockIdx.y * 32;
    const int tx = threadIdx.x, ty = threadIdx.y;
#pragma unroll
    for (int j = 0; j < 4; j++)
        t[ty + j * 8][tx] = in[(size_t)(r0 + ty + j * 8) * Cc + c0 + tx];
    __syncthreads();
#pragma unroll
    for (int j = 0; j < 4; j++) {
        const float v = t[tx][ty + j * 8];
        __nv_bfloat16 h = __float2bfloat16(v);
        __nv_bfloat16 l = __float2bfloat16(v - __bfloat162float(h));
        const size_t o = (size_t)(c0 + ty + j * 8) * R + r0 + tx;
        oh[o] = h;
        ol[o] = l;
    }
}

// ---------------- column softmax (axis=0) on row-major [NS, NKK] ----------------
__global__ void col_pmax(const float* __restrict__ scores, float* __restrict__ pmax)
{
    const int col = blockIdx.x * blockDim.x + threadIdx.x;
    const int r0  = blockIdx.y * 256;
    float m = -3.4e38f;
#pragma unroll 16
    for (int r = 0; r < 256; r++)
        m = fmaxf(m, scores[(size_t)(r0 + r) * NKK + col]);
    pmax[blockIdx.y * NKK + col] = m;
}

__global__ void col_max_reduce(const float* __restrict__ pmax, float* __restrict__ cmax)
{
    const int col = blockIdx.x * blockDim.x + threadIdx.x;
    float m = -3.4e38f;
#pragma unroll
    for (int rc = 0; rc < 32; rc++) m = fmaxf(m, pmax[rc * NKK + col]);
    cmax[col] = m;
}

__global__ void col_psum(const float* __restrict__ scores,
                         const float* __restrict__ cmax, float* __restrict__ psum)
{
    const int col = blockIdx.x * blockDim.x + threadIdx.x;
    const int r0  = blockIdx.y * 256;
    const float mx = cmax[col];
    float s = 0.0f;
#pragma unroll 16
    for (int r = 0; r < 256; r++)
        s += __expf(scores[(size_t)(r0 + r) * NKK + col] - mx);
    psum[blockIdx.y * NKK + col] = s;
}

__global__ void col_sum_reduce(const float* __restrict__ psum, float* __restrict__ crcp)
{
    const int col = blockIdx.x * blockDim.x + threadIdx.x;
    float s = 0.0f;
#pragma unroll
    for (int rc = 0; rc < 32; rc++) s += psum[rc * NKK + col];
    crcp[col] = 1.0f / s;
}

// pass 2: attns = exp(score-max)*rcp in place, fused bf16 hi/lo split output
__global__ void softmax_write_split(float* __restrict__ attns,
                                    const float* __restrict__ cmax,
                                    const float* __restrict__ crcp,
                                    __nv_bfloat16* __restrict__ ah,
                                    __nv_bfloat16* __restrict__ al)
{
    const int col = blockIdx.x * blockDim.x + threadIdx.x;
    const int r0  = blockIdx.y * 32;
    const float mx = cmax[col];
    const float rc = crcp[col];
#pragma unroll
    for (int r = 0; r < 32; r++) {
        const size_t idx = (size_t)(r0 + r) * NKK + col;
        const float v = __expf(attns[idx] - mx) * rc;
        attns[idx] = v;
        __nv_bfloat16 h = __float2bfloat16(v);
        ah[idx] = h;
        al[idx] = __float2bfloat16(v - __bfloat162float(h));
    }
}

// ---------------- launch ----------------
extern "C" void kernel_launch(void* const* d_in, const int* in_sizes, int n_in,
                              void* d_out, int out_size)
{
    (void)in_sizes; (void)n_in; (void)out_size;
    const float* sent  = (const float*)d_in[0];   // [8192, 1024]
    const float* knowl = (const float*)d_in[1];   // [8192, 2048]
    const float* Ws    = (const float*)d_in[2];   // [1024, 1024]
    const float* bs    = (const float*)d_in[3];   // [1024]
    const float* Wk    = (const float*)d_in[4];   // [1024, 2048]
    const float* bk    = (const float*)d_in[5];   // [1024]

    float* attns = (float*)d_out;
    float* fused = attns + (size_t)NS * NKK;

    __nv_bfloat16 *sh, *sl, *wsh, *wsl, *wkh, *wkl, *knh, *knl, *vh, *vl;
    __nv_bfloat16 *Shp, *Slp, *Khp, *Klp, *Ahp, *Alp;
    float *pbuf, *cmaxp, *crcpp;
    cudaGetSymbolAddress((void**)&sh,  g_sh);  cudaGetSymbolAddress((void**)&sl,  g_sl);
    cudaGetSymbolAddress((void**)&wsh, g_wsh); cudaGetSymbolAddress((void**)&wsl, g_wsl);
    cudaGetSymbolAddress((void**)&wkh, g_wkh); cudaGetSymbolAddress((void**)&wkl, g_wkl);
    cudaGetSymbolAddress((void**)&knh, g_knh); cudaGetSymbolAddress((void**)&knl, g_knl);
    cudaGetSymbolAddress((void**)&vh,  g_vh);  cudaGetSymbolAddress((void**)&vl,  g_vl);
    cudaGetSymbolAddress((void**)&Shp, g_Sh);  cudaGetSymbolAddress((void**)&Slp, g_Sl);
    cudaGetSymbolAddress((void**)&Khp, g_Kh);  cudaGetSymbolAddress((void**)&Klp, g_Kl);
    cudaGetSymbolAddress((void**)&Ahp, g_Ah);  cudaGetSymbolAddress((void**)&Alp, g_Al);
    cudaGetSymbolAddress((void**)&pbuf,  g_pbuf);
    cudaGetSymbolAddress((void**)&cmaxp, g_cmax);
    cudaGetSymbolAddress((void**)&crcpp, g_crcp);

    cudaFuncSetAttribute(mma_nt<false>, cudaFuncAttributeMaxDynamicSharedMemorySize, SMEM_MMA);
    cudaFuncSetAttribute(mma_nt<true>,  cudaFuncAttributeMaxDynamicSharedMemorySize, SMEM_MMA);

    // 0) split fp32 operands into bf16 hi/lo
    split2<<<1184, 256>>>(sent,  sh,  sl,  (size_t)NS * HID);
    split2<<<512,  256>>>(Ws,    wsh, wsl, (size_t)HID * HID);
    split2<<<1024, 256>>>(Wk,    wkh, wkl, (size_t)HID * D2);
    split2<<<1184, 256>>>(knowl, knh, knl, (size_t)NKK * D2);
    tsplit<<<dim3(D2 / 32, NKK / 32), dim3(32, 8)>>>(knowl, vh, vl, NKK, D2);

    // 1) S = sent @ Ws^T + bs  -> split directly to Sh/Sl
    mma_nt<true><<<dim3(HID / 128, NS / 128), 256, SMEM_MMA>>>(
        sh, sl, wsh, wsl, bs, nullptr, Shp, Slp, HID, HID);

    // 2) K = knowl @ Wk^T + bk -> split directly to Kh/Kl
    mma_nt<true><<<dim3(HID / 128, NKK / 128), 256, SMEM_MMA>>>(
        knh, knl, wkh, wkl, bk, nullptr, Khp, Klp, HID, D2);

    // 3) scores = S @ K^T -> attns (fp32)
    mma_nt<false><<<dim3(NKK / 128, NS / 128), 256, SMEM_MMA>>>(
        Shp, Slp, Khp, Klp, nullptr, attns, nullptr, nullptr, NKK, HID);

    // 4) column softmax (axis=0), fused split of attns into Ah/Al
    col_pmax          <<<dim3(NKK / 256, 32), 256>>>(attns, pbuf);
    col_max_reduce    <<<NKK / 256, 256>>>(pbuf, cmaxp);
    col_psum          <<<dim3(NKK / 256, 32), 256>>>(attns, cmaxp, pbuf);
    col_sum_reduce    <<<NKK / 256, 256>>>(pbuf, crcpp);
    softmax_write_split<<<dim3(NKK / 256, NS / 32), 256>>>(attns, cmaxp, crcpp, Ahp, Alp);

    // 5) fused = attns @ V  (V^T pre-transposed to [2048, 8192] K-major)
    mma_nt<false><<<dim3(D2 / 128, NS / 128), 256, SMEM_MMA>>>(
        Ahp, Alp, vh, vl, nullptr, fused, nullptr, nullptr, D2, NKK);
}

// round 16
// speedup vs baseline: 3.0943x; 1.0008x over previous
#include <cuda_runtime.h>
#include <cuda_bf16.h>
#include <cstdint>
#include <cstddef>

#define NS   8192
#define NKK  8192
#define HID  1024
#define D2   2048

// ---------------- scratch (module globals; no runtime allocation) ----------------
__device__ __align__(1024) __nv_bfloat16 g_sh[(size_t)NS * HID];
__device__ __align__(1024) __nv_bfloat16 g_sl[(size_t)NS * HID];
__device__ __align__(1024) __nv_bfloat16 g_wsh[(size_t)HID * HID];
__device__ __align__(1024) __nv_bfloat16 g_wsl[(size_t)HID * HID];
__device__ __align__(1024) __nv_bfloat16 g_wkh[(size_t)HID * D2];
__device__ __align__(1024) __nv_bfloat16 g_wkl[(size_t)HID * D2];
__device__ __align__(1024) __nv_bfloat16 g_knh[(size_t)NKK * D2];
__device__ __align__(1024) __nv_bfloat16 g_knl[(size_t)NKK * D2];
__device__ __align__(1024) __nv_bfloat16 g_vh[(size_t)D2 * NKK];
__device__ __align__(1024) __nv_bfloat16 g_vl[(size_t)D2 * NKK];
__device__ __align__(1024) __nv_bfloat16 g_Sh[(size_t)NS * HID];
__device__ __align__(1024) __nv_bfloat16 g_Sl[(size_t)NS * HID];
__device__ __align__(1024) __nv_bfloat16 g_Kh[(size_t)NKK * HID];
__device__ __align__(1024) __nv_bfloat16 g_Kl[(size_t)NKK * HID];
__device__ __align__(1024) __nv_bfloat16 g_Ah[(size_t)NS * NKK];
__device__ __align__(1024) __nv_bfloat16 g_Al[(size_t)NS * NKK];
__device__ float g_pbuf[32 * NKK];
__device__ float g_cmax[NKK];
__device__ float g_crcp[NKK];

// ---------------- low-level helpers (sm_80-era PTX only: safe on compute_103) ----
__device__ __forceinline__ uint32_t s2u(const void* p) {
    uint32_t a;
    asm("{ .reg .u64 t; cvta.to.shared.u64 t, %1; cvt.u32.u64 %0, t; }"
        : "=r"(a) : "l"(p));
    return a;
}

__device__ __forceinline__ void ldsm4(uint32_t* r, uint32_t addr) {
    asm volatile("ldmatrix.sync.aligned.m8n8.x4.shared.b16 {%0,%1,%2,%3}, [%4];"
                 : "=r"(r[0]), "=r"(r[1]), "=r"(r[2]), "=r"(r[3]) : "r"(addr));
}

__device__ __forceinline__ void mma16816(float* c, const uint32_t* a, const uint32_t* b) {
    asm volatile(
        "mma.sync.aligned.m16n8k16.row.col.f32.bf16.bf16.f32 "
        "{%0,%1,%2,%3}, {%4,%5,%6,%7}, {%8,%9}, {%0,%1,%2,%3};"
        : "+f"(c[0]), "+f"(c[1]), "+f"(c[2]), "+f"(c[3])
        : "r"(a[0]), "r"(a[1]), "r"(a[2]), "r"(a[3]), "r"(b[0]), "r"(b[1]));
}

// SW128 swizzle of a (row*128 + kb) byte offset within a 128B-row tile.
// For kb < 128: sw = row*128 + (kb ^ ((row&7)<<4)).
__device__ __forceinline__ uint32_t swz(int row, int kb) {
    return (uint32_t)(row * 128 + (kb ^ ((row & 7) << 4)));
}

static constexpr int TILE = 16384;                    // 128 rows x 128 bytes
static constexpr int SMEM_MMA = 2 * 4 * TILE;         // 2 stages x 4 half-tiles = 128KB

// load one 128-row x 64-bf16 (128B/row) K-major tile via cp.async, SW128 swizzle.
// 256 threads, 1024 16B-chunks -> 4 iterations.
__device__ __forceinline__ void load_half_tile(uint32_t sdst,
                                               const __nv_bfloat16* __restrict__ g,
                                               int ld, int row0, int k0, int tid) {
#pragma unroll
    for (int i = 0; i < 4; i++) {
        const int idx = i * 256 + tid;        // 0..1023
        const int row = idx >> 3;             // 0..127
        const int kb  = (idx & 7) * 16;       // 0..112 bytes
        const __nv_bfloat16* gp = g + (size_t)(row0 + row) * ld + k0 + (kb >> 1);
        asm volatile("cp.async.cg.shared.global [%0], [%1], 16;\n"
                     :: "r"(sdst + swz(row, kb)), "l"(gp));
    }
}

// ---------------- split-bf16 HMMA NT GEMM ----------------
// C[M,N] = (Ah+Al)[M,Kd] @ (Bh+Bl)[N,Kd]^T (+bias).
// SPLIT_OUT: emit bf16 hi/lo pair (Ch, Cl) instead of fp32 C.
template<bool SPLIT_OUT>
__global__ __launch_bounds__(256, 1)
void mma_nt(const __nv_bfloat16* __restrict__ Ahp, const __nv_bfloat16* __restrict__ Alp,
            const __nv_bfloat16* __restrict__ Bhp, const __nv_bfloat16* __restrict__ Blp,
            const float* __restrict__ bias, float* __restrict__ C,
            __nv_bfloat16* __restrict__ Ch, __nv_bfloat16* __restrict__ Cl,
            int N, int Kd)
{
    extern __shared__ char smem[];
    const int tid  = threadIdx.x;
    const int wid  = tid >> 5;
    const int lane = tid & 31;
    const int bm = blockIdx.y * 128, bn = blockIdx.x * 128;

    // warp grid: 2 (m) x 4 (n); warp tile 64 (m) x 32 (n)
    const int wm0 = (wid & 1) * 64;
    const int wn0 = (wid >> 1) * 32;

    const uint32_t sb  = s2u(smem);
    const uint32_t st[2] = { sb, sb + 4 * TILE };

    float acc[4][4][4];
#pragma unroll
    for (int i = 0; i < 4; i++)
#pragma unroll
        for (int j = 0; j < 4; j++)
#pragma unroll
            for (int q = 0; q < 4; q++) acc[i][j][q] = 0.0f;

    // per-thread ldmatrix address components (row-dependent parts)
    // A: row = wm0 + mi*16 + (lane&15); k-halve select = lane>>4
    uint32_t aOff[4];
#pragma unroll
    for (int mi = 0; mi < 4; mi++) {
        const int r = wm0 + mi * 16 + (lane & 15);
        aOff[mi] = (uint32_t)(r * 128) ;
    }
    const uint32_t aXor = (uint32_t)(((wm0 + (lane & 15)) & 7) << 4);
    const int aKhb = (lane >> 4) * 16;       // 0 or 16 bytes
    // B: row = wn0 + npair*16 + ((lane>>4)&1)*8 + (lane&7); k-halve = (lane>>3)&1
    uint32_t bOff[2];
    const int bRowBase = wn0 + ((lane >> 4) & 1) * 8 + (lane & 7);
#pragma unroll
    for (int p = 0; p < 2; p++)
        bOff[p] = (uint32_t)((bRowBase + p * 16) * 128);
    const uint32_t bXor = (uint32_t)((bRowBase & 7) << 4);
    const int bKhb = ((lane >> 3) & 1) * 16;

    const int NC = Kd >> 6;   // 64-wide K chunks

    // prologue: stage 0 (chunk 0), stage 1 (chunk 1)
    load_half_tile(st[0],            Ahp, Kd, bm, 0, tid);
    load_half_tile(st[0] + TILE,     Alp, Kd, bm, 0, tid);
    load_half_tile(st[0] + 2 * TILE, Bhp, Kd, bn, 0, tid);
    load_half_tile(st[0] + 3 * TILE, Blp, Kd, bn, 0, tid);
    asm volatile("cp.async.commit_group;" ::: "memory");
    if (NC > 1) {
        load_half_tile(st[1],            Ahp, Kd, bm, 64, tid);
        load_half_tile(st[1] + TILE,     Alp, Kd, bm, 64, tid);
        load_half_tile(st[1] + 2 * TILE, Bhp, Kd, bn, 64, tid);
        load_half_tile(st[1] + 3 * TILE, Blp, Kd, bn, 64, tid);
        asm volatile("cp.async.commit_group;" ::: "memory");
    }

    for (int c = 0; c < NC; c++) {
        if (c + 1 < NC) { asm volatile("cp.async.wait_group 1;" ::: "memory"); }
        else            { asm volatile("cp.async.wait_group 0;" ::: "memory"); }
        __syncthreads();

        const uint32_t base = st[c & 1];
#pragma unroll
        for (int ks = 0; ks < 4; ks++) {
            const int kb = ks * 32;
            uint32_t ah[4][4], al[4][4], bh[2][4], bl[2][4];
#pragma unroll
            for (int mi = 0; mi < 4; mi++) {
                const uint32_t ad = base + aOff[mi] + (uint32_t)((kb + aKhb) ^ aXor);
                ldsm4(ah[mi], ad);
                ldsm4(al[mi], ad + TILE);
            }
#pragma unroll
            for (int p = 0; p < 2; p++) {
                const uint32_t bd = base + 2 * TILE + bOff[p] + (uint32_t)((kb + bKhb) ^ bXor);
                ldsm4(bh[p], bd);
                ldsm4(bl[p], bd + TILE);
            }
#pragma unroll
            for (int mi = 0; mi < 4; mi++)
#pragma unroll
                for (int ni = 0; ni < 4; ni++) {
                    const uint32_t* bhp = &bh[ni >> 1][(ni & 1) * 2];
                    const uint32_t* blp = &bl[ni >> 1][(ni & 1) * 2];
                    mma16816(acc[mi][ni], ah[mi], bhp);
                    mma16816(acc[mi][ni], ah[mi], blp);
                    mma16816(acc[mi][ni], al[mi], bhp);
                }
        }
        __syncthreads();

        if (c + 2 < NC) {
            const uint32_t b2 = st[c & 1];
            const int k0 = (c + 2) << 6;
            load_half_tile(b2,            Ahp, Kd, bm, k0, tid);
            load_half_tile(b2 + TILE,     Alp, Kd, bm, k0, tid);
            load_half_tile(b2 + 2 * TILE, Bhp, Kd, bn, k0, tid);
            load_half_tile(b2 + 3 * TILE, Blp, Kd, bn, k0, tid);
            asm volatile("cp.async.commit_group;" ::: "memory");
        }
    }

    // ---------------- epilogue ----------------
    const bool hb = (bias != nullptr);
#pragma unroll
    for (int mi = 0; mi < 4; mi++) {
#pragma unroll
        for (int half = 0; half < 2; half++) {
            const int row = bm + wm0 + mi * 16 + (lane >> 2) + half * 8;
#pragma unroll
            for (int ni = 0; ni < 4; ni++) {
                const int col = bn + wn0 + ni * 8 + (lane & 3) * 2;
                float v0 = acc[mi][ni][half * 2 + 0];
                float v1 = acc[mi][ni][half * 2 + 1];
                if (hb) { v0 += bias[col]; v1 += bias[col + 1]; }
                const size_t idx = (size_t)row * N + col;
                if (SPLIT_OUT) {
                    __nv_bfloat16 h0 = __float2bfloat16(v0);
                    __nv_bfloat16 h1 = __float2bfloat16(v1);
                    __nv_bfloat16 l0 = __float2bfloat16(v0 - __bfloat162float(h0));
                    __nv_bfloat16 l1 = __float2bfloat16(v1 - __bfloat162float(h1));
                    *reinterpret_cast<__nv_bfloat162*>(Ch + idx) = __halves2bfloat162(h0, h1);
                    *reinterpret_cast<__nv_bfloat162*>(Cl + idx) = __halves2bfloat162(l0, l1);
                } else {
                    float2 v; v.x = v0; v.y = v1;
                    *reinterpret_cast<float2*>(C + idx) = v;
                }
            }
        }
    }
}

// ---------------- fp32 -> bf16 hi/lo split (elementwise) ----------------
__global__ void split2(const float* __restrict__ x, __nv_bfloat16* __restrict__ h,
                       __nv_bfloat16* __restrict__ l, size_t n)
{
    const size_t stride = (size_t)gridDim.x * blockDim.x * 4;
    for (size_t j = ((size_t)blockIdx.x * blockDim.x + threadIdx.x) * 4; j < n; j += stride) {
        float4 v = *reinterpret_cast<const float4*>(x + j);
        __nv_bfloat16 h0 = __float2bfloat16(v.x), h1 = __float2bfloat16(v.y);
        __nv_bfloat16 h2 = __float2bfloat16(v.z), h3 = __float2bfloat16(v.w);
        __nv_bfloat16 l0 = __float2bfloat16(v.x - __bfloat162float(h0));
        __nv_bfloat16 l1 = __float2bfloat16(v.y - __bfloat162float(h1));
        __nv_bfloat16 l2 = __float2bfloat16(v.z - __bfloat162float(h2));
        __nv_bfloat16 l3 = __float2bfloat16(v.w - __bfloat162float(h3));
        *reinterpret_cast<__nv_bfloat162*>(h + j)     = __halves2bfloat162(h0, h1);
        *reinterpret_cast<__nv_bfloat162*>(h + j + 2) = __halves2bfloat162(h2, h3);
        *reinterpret_cast<__nv_bfloat162*>(l + j)     = __halves2bfloat162(l0, l1);
        *reinterpret_cast<__nv_bfloat162*>(l + j + 2) = __halves2bfloat162(l2, l3);
    }
}

// ---------------- transpose + split: knowl [R,Cc] -> vh/vl [Cc,R] ----------------
__global__ void tsplit(const float* __restrict__ in, __nv_bfloat16* __restrict__ oh,
                       __nv_bfloat16* __restrict__ ol, int R, int Cc)
{
    __shared__ float t[32][33];
    const int c0 = blockIdx.x * 32, r0 = blockIdx.y * 32;
    const int tx = threadIdx.x, ty = threadIdx.y;
#pragma unroll
    for (int j = 0; j < 4; j++)
        t[ty + j * 8][tx] = in[(size_t)(r0 + ty + j * 8) * Cc + c0 + tx];
    __syncthreads();
#pragma unroll
    for (int j = 0; j < 4; j++) {
        const float v = t[tx][ty + j * 8];
        __nv_bfloat16 h = __float2bfloat16(v);
        __nv_bfloat16 l = __float2bfloat16(v - __bfloat162float(h));
        const size_t o = (size_t)(c0 + ty + j * 8) * R + r0 + tx;
        oh[o] = h;
        ol[o] = l;
    }
}

// ---------------- column softmax (axis=0) on row-major [NS, NKK] ----------------
__global__ void col_pmax(const float* __restrict__ scores, float* __restrict__ pmax)
{
    const int col = blockIdx.x * blockDim.x + threadIdx.x;
    const int r0  = blockIdx.y * 256;
    float m = -3.4e38f;
#pragma unroll 16
    for (int r = 0; r < 256; r++)
        m = fmaxf(m, scores[(size_t)(r0 + r) * NKK + col]);
    pmax[blockIdx.y * NKK + col] = m;
}

__global__ void col_max_reduce(const float* __restrict__ pmax, float* __restrict__ cmax)
{
    const int col = blockIdx.x * blockDim.x + threadIdx.x;
    float m = -3.4e38f;
#pragma unroll
    for (int rc = 0; rc < 32; rc++) m = fmaxf(m, pmax[rc * NKK + col]);
    cmax[col] = m;
}

__global__ void col_psum(const float* __restrict__ scores,
                         const float* __restrict__ cmax, float* __restrict__ psum)
{
    const int col = blockIdx.x * blockDim.x + threadIdx.x;
    const int r0  = blockIdx.y * 256;
    const float mx = cmax[col];
    float s = 0.0f;
#pragma unroll 16
    for (int r = 0; r < 256; r++)
        s += __expf(scores[(size_t)(r0 + r) * NKK + col] - mx);
    psum[blockIdx.y * NKK + col] = s;
}

__global__ void col_sum_reduce(const float* __restrict__ psum, float* __restrict__ crcp)
{
    const int col = blockIdx.x * blockDim.x + threadIdx.x;
    float s = 0.0f;
#pragma unroll
    for (int rc = 0; rc < 32; rc++) s += psum[rc * NKK + col];
    crcp[col] = 1.0f / s;
}

// pass 2: attns = exp(score-max)*rcp in place, fused bf16 hi/lo split output
__global__ void softmax_write_split(float* __restrict__ attns,
                                    const float* __restrict__ cmax,
                                    const float* __restrict__ crcp,
                                    __nv_bfloat16* __restrict__ ah,
                                    __nv_bfloat16* __restrict__ al)
{
    const int col = blockIdx.x * blockDim.x + threadIdx.x;
    const int r0  = blockIdx.y * 32;
    const float mx = cmax[col];
    const float rc = crcp[col];
#pragma unroll
    for (int r = 0; r < 32; r++) {
        const size_t idx = (size_t)(r0 + r) * NKK + col;
        const float v = __expf(attns[idx] - mx) * rc;
        attns[idx] = v;
        __nv_bfloat16 h = __float2bfloat16(v);
        ah[idx] = h;
        al[idx] = __float2bfloat16(v - __bfloat162float(h));
    }
}

// ---------------- launch ----------------
extern "C" void kernel_launch(void* const* d_in, const int* in_sizes, int n_in,
                              void* d_out, int out_size)
{
    (void)in_sizes; (void)n_in; (void)out_size;
    const float* sent  = (const float*)d_in[0];   // [8192, 1024]
    const float* knowl = (const float*)d_in[1];   // [8192, 2048]
    const float* Ws    = (const float*)d_in[2];   // [1024, 1024]
    const float* bs    = (const float*)d_in[3];   // [1024]
    const float* Wk    = (const float*)d_in[4];   // [1024, 2048]
    const float* bk    = (const float*)d_in[5];   // [1024]

    float* attns = (float*)d_out;
    float* fused = attns + (size_t)NS * NKK;

    __nv_bfloat16 *sh, *sl, *wsh, *wsl, *wkh, *wkl, *knh, *knl, *vh, *vl;
    __nv_bfloat16 *Shp, *Slp, *Khp, *Klp, *Ahp, *Alp;
    float *pbuf, *cmaxp, *crcpp;
    cudaGetSymbolAddress((void**)&sh,  g_sh);  cudaGetSymbolAddress((void**)&sl,  g_sl);
    cudaGetSymbolAddress((void**)&wsh, g_wsh); cudaGetSymbolAddress((void**)&wsl, g_wsl);
    cudaGetSymbolAddress((void**)&wkh, g_wkh); cudaGetSymbolAddress((void**)&wkl, g_wkl);
    cudaGetSymbolAddress((void**)&knh, g_knh); cudaGetSymbolAddress((void**)&knl, g_knl);
    cudaGetSymbolAddress((void**)&vh,  g_vh);  cudaGetSymbolAddress((void**)&vl,  g_vl);
    cudaGetSymbolAddress((void**)&Shp, g_Sh);  cudaGetSymbolAddress((void**)&Slp, g_Sl);
    cudaGetSymbolAddress((void**)&Khp, g_Kh);  cudaGetSymbolAddress((void**)&Klp, g_Kl);
    cudaGetSymbolAddress((void**)&Ahp, g_Ah);  cudaGetSymbolAddress((void**)&Alp, g_Al);
    cudaGetSymbolAddress((void**)&pbuf,  g_pbuf);
    cudaGetSymbolAddress((void**)&cmaxp, g_cmax);
    cudaGetSymbolAddress((void**)&crcpp, g_crcp);

    cudaFuncSetAttribute(mma_nt<false>, cudaFuncAttributeMaxDynamicSharedMemorySize, SMEM_MMA);
    cudaFuncSetAttribute(mma_nt<true>,  cudaFuncAttributeMaxDynamicSharedMemorySize, SMEM_MMA);

    // 0) split fp32 operands into bf16 hi/lo
    split2<<<1184, 256>>>(sent,  sh,  sl,  (size_t)NS * HID);
    split2<<<512,  256>>>(Ws,    wsh, wsl, (size_t)HID * HID);
    split2<<<1024, 256>>>(Wk,    wkh, wkl, (size_t)HID * D2);
    split2<<<1184, 256>>>(knowl, knh, knl, (size_t)NKK * D2);
    tsplit<<<dim3(D2 / 32, NKK / 32), dim3(32, 8)>>>(knowl, vh, vl, NKK, D2);

    // 1) S = sent @ Ws^T + bs  -> split directly to Sh/Sl
    mma_nt<true><<<dim3(HID / 128, NS / 128), 256, SMEM_MMA>>>(
        sh, sl, wsh, wsl, bs, nullptr, Shp, Slp, HID, HID);

    // 2) K = knowl @ Wk^T + bk -> split directly to Kh/Kl
    mma_nt<true><<<dim3(HID / 128, NKK / 128), 256, SMEM_MMA>>>(
        knh, knl, wkh, wkl, bk, nullptr, Khp, Klp, HID, D2);

    // 3) scores = S @ K^T -> attns (fp32)
    mma_nt<false><<<dim3(NKK / 128, NS / 128), 256, SMEM_MMA>>>(
        Shp, Slp, Khp, Klp, nullptr, attns, nullptr, nullptr, NKK, HID);

    // 4) column softmax (axis=0), fused split of attns into Ah/Al
    col_pmax          <<<dim3(NKK / 256, 32), 256>>>(attns, pbuf);
    col_max_reduce    <<<NKK / 256, 256>>>(pbuf, cmaxp);
    col_psum          <<<dim3(NKK / 256, 32), 256>>>(attns, cmaxp, pbuf);
    col_sum_reduce    <<<NKK / 256, 256>>>(pbuf, crcpp);
    softmax_write_split<<<dim3(NKK / 256, NS / 32), 256>>>(attns, cmaxp, crcpp, Ahp, Alp);

    // 5) fused = attns @ V  (V^T pre-transposed to [2048, 8192] K-major)
    mma_nt<false><<<dim3(D2 / 128, NS / 128), 256, SMEM_MMA>>>(
        Ahp, Alp, vh, vl, nullptr, fused, nullptr, nullptr, D2, NKK);
}

// round 17
// speedup vs baseline: 3.5982x; 1.1628x over previous
#include <cuda_runtime.h>
#include <cuda_bf16.h>
#include <cuda_fp16.h>
#include <cstdint>
#include <cstddef>

#define NS   8192
#define NKK  8192
#define HID  1024
#define D2   2048

// ---------------- scratch (module globals; no runtime allocation) ----------------
__device__ __align__(1024) __nv_bfloat16 g_sh[(size_t)NS * HID];
__device__ __align__(1024) __nv_bfloat16 g_sl[(size_t)NS * HID];
__device__ __align__(1024) __nv_bfloat16 g_wsh[(size_t)HID * HID];
__device__ __align__(1024) __nv_bfloat16 g_wsl[(size_t)HID * HID];
__device__ __align__(1024) __nv_bfloat16 g_wkh[(size_t)HID * D2];
__device__ __align__(1024) __nv_bfloat16 g_wkl[(size_t)HID * D2];
__device__ __align__(1024) __nv_bfloat16 g_knh[(size_t)NKK * D2];
__device__ __align__(1024) __nv_bfloat16 g_knl[(size_t)NKK * D2];
__device__ __align__(1024) __half        g_vh[(size_t)D2 * NKK];   // V^T fp16
__device__ __align__(1024) __nv_bfloat16 g_Sh[(size_t)NS * HID];
__device__ __align__(1024) __nv_bfloat16 g_Sl[(size_t)NS * HID];
__device__ __align__(1024) __nv_bfloat16 g_Kh[(size_t)NKK * HID];
__device__ __align__(1024) __nv_bfloat16 g_Kl[(size_t)NKK * HID];
__device__ __align__(1024) __half        g_Ah[(size_t)NS * NKK];   // attns fp16 hi
__device__ __align__(1024) __half        g_Al[(size_t)NS * NKK];   // attns fp16 lo
__device__ float g_pbuf[32 * NKK];
__device__ float g_cmax[NKK];
__device__ float g_crcp[NKK];

// ---------------- low-level helpers (sm_80-era PTX only: safe on compute_103) ----
__device__ __forceinline__ uint32_t s2u(const void* p) {
    uint32_t a;
    asm("{ .reg .u64 t; cvta.to.shared.u64 t, %1; cvt.u32.u64 %0, t; }"
        : "=r"(a) : "l"(p));
    return a;
}

__device__ __forceinline__ void ldsm4(uint32_t* r, uint32_t addr) {
    asm volatile("ldmatrix.sync.aligned.m8n8.x4.shared.b16 {%0,%1,%2,%3}, [%4];"
                 : "=r"(r[0]), "=r"(r[1]), "=r"(r[2]), "=r"(r[3]) : "r"(addr));
}

__device__ __forceinline__ void mma_bf16(float* c, const uint32_t* a, const uint32_t* b) {
    asm volatile(
        "mma.sync.aligned.m16n8k16.row.col.f32.bf16.bf16.f32 "
        "{%0,%1,%2,%3}, {%4,%5,%6,%7}, {%8,%9}, {%0,%1,%2,%3};"
        : "+f"(c[0]), "+f"(c[1]), "+f"(c[2]), "+f"(c[3])
        : "r"(a[0]), "r"(a[1]), "r"(a[2]), "r"(a[3]), "r"(b[0]), "r"(b[1]));
}

__device__ __forceinline__ void mma_f16(float* c, const uint32_t* a, const uint32_t* b) {
    asm volatile(
        "mma.sync.aligned.m16n8k16.row.col.f32.f16.f16.f32 "
        "{%0,%1,%2,%3}, {%4,%5,%6,%7}, {%8,%9}, {%0,%1,%2,%3};"
        : "+f"(c[0]), "+f"(c[1]), "+f"(c[2]), "+f"(c[3])
        : "r"(a[0]), "r"(a[1]), "r"(a[2]), "r"(a[3]), "r"(b[0]), "r"(b[1]));
}

// SW128 swizzle of (row*128 + kb) byte offset within a 128B-row tile.
__device__ __forceinline__ uint32_t swz(int row, int kb) {
    return (uint32_t)(row * 128 + (kb ^ ((row & 7) << 4)));
}

static constexpr int TILE = 16384;                     // 128 rows x 128 bytes
static constexpr int SMEM_BF16 = 3 * 4 * TILE;         // 3 stages x 4 half-tiles = 192KB
static constexpr int SMEM_F16  = 3 * 3 * TILE;         // 3 stages x 3 half-tiles = 144KB

// load one 128-row x 64-elem (128B/row) K-major tile via cp.async, SW128 swizzle.
template<typename T>
__device__ __forceinline__ void load_half_tile(uint32_t sdst,
                                               const T* __restrict__ g,
                                               int ld, int row0, int k0, int tid) {
#pragma unroll
    for (int i = 0; i < 4; i++) {
        const int idx = i * 256 + tid;        // 0..1023
        const int row = idx >> 3;             // 0..127
        const int kb  = (idx & 7) * 16;       // 0..112 bytes
        const T* gp = g + (size_t)(row0 + row) * ld + k0 + (kb >> 1);
        asm volatile("cp.async.cg.shared.global [%0], [%1], 16;\n"
                     :: "r"(sdst + swz(row, kb)), "l"(gp));
    }
}

// ---------------- split-bf16 HMMA NT GEMM (3-product, 3-stage pipeline) ----------
// C[M,N] = (Ah+Al)[M,Kd] @ (Bh+Bl)[N,Kd]^T (+bias).
// SPLIT_OUT: emit bf16 hi/lo pair (Ch, Cl) instead of fp32 C.
template<bool SPLIT_OUT>
__global__ __launch_bounds__(256, 1)
void mma_nt(const __nv_bfloat16* __restrict__ Ahp, const __nv_bfloat16* __restrict__ Alp,
            const __nv_bfloat16* __restrict__ Bhp, const __nv_bfloat16* __restrict__ Blp,
            const float* __restrict__ bias, float* __restrict__ C,
            __nv_bfloat16* __restrict__ Ch, __nv_bfloat16* __restrict__ Cl,
            int N, int Kd)
{
    extern __shared__ char smem[];
    const int tid  = threadIdx.x;
    const int wid  = tid >> 5;
    const int lane = tid & 31;
    const int bm = blockIdx.y * 128, bn = blockIdx.x * 128;

    // warp grid: 2 (m) x 4 (n); warp tile 64 (m) x 32 (n)
    const int wm0 = (wid & 1) * 64;
    const int wn0 = (wid >> 1) * 32;

    const uint32_t sb = s2u(smem);
    const uint32_t STAGE = 4 * TILE;
    const uint32_t st[3] = { sb, sb + STAGE, sb + 2 * STAGE };

    float acc[4][4][4];
#pragma unroll
    for (int i = 0; i < 4; i++)
#pragma unroll
        for (int j = 0; j < 4; j++)
#pragma unroll
            for (int q = 0; q < 4; q++) acc[i][j][q] = 0.0f;

    uint32_t aOff[4];
#pragma unroll
    for (int mi = 0; mi < 4; mi++)
        aOff[mi] = (uint32_t)((wm0 + mi * 16 + (lane & 15)) * 128);
    const uint32_t aXor = (uint32_t)(((wm0 + (lane & 15)) & 7) << 4);
    const int aKhb = (lane >> 4) * 16;
    uint32_t bOff[2];
    const int bRowBase = wn0 + ((lane >> 4) & 1) * 8 + (lane & 7);
#pragma unroll
    for (int p = 0; p < 2; p++)
        bOff[p] = (uint32_t)((bRowBase + p * 16) * 128);
    const uint32_t bXor = (uint32_t)((bRowBase & 7) << 4);
    const int bKhb = ((lane >> 3) & 1) * 16;

    const int NC = Kd >> 6;   // 64-wide K chunks (always >= 16 here)

    // prologue: chunks 0,1 -> stages 0,1
#pragma unroll
    for (int p = 0; p < 2; p++) {
        load_half_tile(st[p],            Ahp, Kd, bm, p * 64, tid);
        load_half_tile(st[p] + TILE,     Alp, Kd, bm, p * 64, tid);
        load_half_tile(st[p] + 2 * TILE, Bhp, Kd, bn, p * 64, tid);
        load_half_tile(st[p] + 3 * TILE, Blp, Kd, bn, p * 64, tid);
        asm volatile("cp.async.commit_group;" ::: "memory");
    }

    int cm = 0, ldst = 2;
    for (int c = 0; c < NC; c++) {
        if (c + 1 < NC) { asm volatile("cp.async.wait_group 1;" ::: "memory"); }
        else            { asm volatile("cp.async.wait_group 0;" ::: "memory"); }
        __syncthreads();

        // issue loads for chunk c+2 into stage ldst (last read at chunk c-1)
        if (c + 2 < NC) {
            const uint32_t b2 = st[ldst];
            const int k0 = (c + 2) << 6;
            load_half_tile(b2,            Ahp, Kd, bm, k0, tid);
            load_half_tile(b2 + TILE,     Alp, Kd, bm, k0, tid);
            load_half_tile(b2 + 2 * TILE, Bhp, Kd, bn, k0, tid);
            load_half_tile(b2 + 3 * TILE, Blp, Kd, bn, k0, tid);
            asm volatile("cp.async.commit_group;" ::: "memory");
        }

        const uint32_t base = st[cm];
#pragma unroll
        for (int ks = 0; ks < 4; ks++) {
            const int kb = ks * 32;
            uint32_t ah[4][4], al[4][4], bh[2][4], bl[2][4];
#pragma unroll
            for (int mi = 0; mi < 4; mi++) {
                const uint32_t ad = base + aOff[mi] + (uint32_t)((kb + aKhb) ^ aXor);
                ldsm4(ah[mi], ad);
                ldsm4(al[mi], ad + TILE);
            }
#pragma unroll
            for (int p = 0; p < 2; p++) {
                const uint32_t bd = base + 2 * TILE + bOff[p] + (uint32_t)((kb + bKhb) ^ bXor);
                ldsm4(bh[p], bd);
                ldsm4(bl[p], bd + TILE);
            }
#pragma unroll
            for (int mi = 0; mi < 4; mi++)
#pragma unroll
                for (int ni = 0; ni < 4; ni++) {
                    const uint32_t* bhp = &bh[ni >> 1][(ni & 1) * 2];
                    const uint32_t* blp = &bl[ni >> 1][(ni & 1) * 2];
                    mma_bf16(acc[mi][ni], ah[mi], bhp);
                    mma_bf16(acc[mi][ni], ah[mi], blp);
                    mma_bf16(acc[mi][ni], al[mi], bhp);
                }
        }
        cm = (cm == 2) ? 0 : cm + 1;
        ldst = (ldst == 2) ? 0 : ldst + 1;
    }

    // ---------------- epilogue ----------------
    const bool hb = (bias != nullptr);
#pragma unroll
    for (int mi = 0; mi < 4; mi++) {
#pragma unroll
        for (int half = 0; half < 2; half++) {
            const int row = bm + wm0 + mi * 16 + (lane >> 2) + half * 8;
#pragma unroll
            for (int ni = 0; ni < 4; ni++) {
                const int col = bn + wn0 + ni * 8 + (lane & 3) * 2;
                float v0 = acc[mi][ni][half * 2 + 0];
                float v1 = acc[mi][ni][half * 2 + 1];
                if (hb) { v0 += bias[col]; v1 += bias[col + 1]; }
                const size_t idx = (size_t)row * N + col;
                if (SPLIT_OUT) {
                    __nv_bfloat16 h0 = __float2bfloat16(v0);
                    __nv_bfloat16 h1 = __float2bfloat16(v1);
                    __nv_bfloat16 l0 = __float2bfloat16(v0 - __bfloat162float(h0));
                    __nv_bfloat16 l1 = __float2bfloat16(v1 - __bfloat162float(h1));
                    *reinterpret_cast<__nv_bfloat162*>(Ch + idx) = __halves2bfloat162(h0, h1);
                    *reinterpret_cast<__nv_bfloat162*>(Cl + idx) = __halves2bfloat162(l0, l1);
                } else {
                    float2 v; v.x = v0; v.y = v1;
                    *reinterpret_cast<float2*>(C + idx) = v;
                }
            }
        }
    }
}

// ---------------- fp16 2-product HMMA NT GEMM (GEMM5) ----------------
// C[M,N] = (Ah+Al)[M,Kd] @ Bh[N,Kd]^T; Ah/Al fp16 pair, Bh single fp16.
__global__ __launch_bounds__(256, 1)
void mma_nt_f16(const __half* __restrict__ Ahp, const __half* __restrict__ Alp,
                const __half* __restrict__ Bhp, float* __restrict__ C,
                int N, int Kd)
{
    extern __shared__ char smem[];
    const int tid  = threadIdx.x;
    const int wid  = tid >> 5;
    const int lane = tid & 31;
    const int bm = blockIdx.y * 128, bn = blockIdx.x * 128;
    const int wm0 = (wid & 1) * 64;
    const int wn0 = (wid >> 1) * 32;

    const uint32_t sb = s2u(smem);
    const uint32_t STAGE = 3 * TILE;
    const uint32_t st[3] = { sb, sb + STAGE, sb + 2 * STAGE };

    float acc[4][4][4];
#pragma unroll
    for (int i = 0; i < 4; i++)
#pragma unroll
        for (int j = 0; j < 4; j++)
#pragma unroll
            for (int q = 0; q < 4; q++) acc[i][j][q] = 0.0f;

    uint32_t aOff[4];
#pragma unroll
    for (int mi = 0; mi < 4; mi++)
        aOff[mi] = (uint32_t)((wm0 + mi * 16 + (lane & 15)) * 128);
    const uint32_t aXor = (uint32_t)(((wm0 + (lane & 15)) & 7) << 4);
    const int aKhb = (lane >> 4) * 16;
    uint32_t bOff[2];
    const int bRowBase = wn0 + ((lane >> 4) & 1) * 8 + (lane & 7);
#pragma unroll
    for (int p = 0; p < 2; p++)
        bOff[p] = (uint32_t)((bRowBase + p * 16) * 128);
    const uint32_t bXor = (uint32_t)((bRowBase & 7) << 4);
    const int bKhb = ((lane >> 3) & 1) * 16;

    const int NC = Kd >> 6;

#pragma unroll
    for (int p = 0; p < 2; p++) {
        load_half_tile(st[p],            Ahp, Kd, bm, p * 64, tid);
        load_half_tile(st[p] + TILE,     Alp, Kd, bm, p * 64, tid);
        load_half_tile(st[p] + 2 * TILE, Bhp, Kd, bn, p * 64, tid);
        asm volatile("cp.async.commit_group;" ::: "memory");
    }

    int cm = 0, ldst = 2;
    for (int c = 0; c < NC; c++) {
        if (c + 1 < NC) { asm volatile("cp.async.wait_group 1;" ::: "memory"); }
        else            { asm volatile("cp.async.wait_group 0;" ::: "memory"); }
        __syncthreads();

        if (c + 2 < NC) {
            const uint32_t b2 = st[ldst];
            const int k0 = (c + 2) << 6;
            load_half_tile(b2,            Ahp, Kd, bm, k0, tid);
            load_half_tile(b2 + TILE,     Alp, Kd, bm, k0, tid);
            load_half_tile(b2 + 2 * TILE, Bhp, Kd, bn, k0, tid);
            asm volatile("cp.async.commit_group;" ::: "memory");
        }

        const uint32_t base = st[cm];
#pragma unroll
        for (int ks = 0; ks < 4; ks++) {
            const int kb = ks * 32;
            uint32_t ah[4][4], al[4][4], bh[2][4];
#pragma unroll
            for (int mi = 0; mi < 4; mi++) {
                const uint32_t ad = base + aOff[mi] + (uint32_t)((kb + aKhb) ^ aXor);
                ldsm4(ah[mi], ad);
                ldsm4(al[mi], ad + TILE);
            }
#pragma unroll
            for (int p = 0; p < 2; p++) {
                const uint32_t bd = base + 2 * TILE + bOff[p] + (uint32_t)((kb + bKhb) ^ bXor);
                ldsm4(bh[p], bd);
            }
#pragma unroll
            for (int mi = 0; mi < 4; mi++)
#pragma unroll
                for (int ni = 0; ni < 4; ni++) {
                    const uint32_t* bhp = &bh[ni >> 1][(ni & 1) * 2];
                    mma_f16(acc[mi][ni], ah[mi], bhp);
                    mma_f16(acc[mi][ni], al[mi], bhp);
                }
        }
        cm = (cm == 2) ? 0 : cm + 1;
        ldst = (ldst == 2) ? 0 : ldst + 1;
    }

#pragma unroll
    for (int mi = 0; mi < 4; mi++) {
#pragma unroll
        for (int half = 0; half < 2; half++) {
            const int row = bm + wm0 + mi * 16 + (lane >> 2) + half * 8;
#pragma unroll
            for (int ni = 0; ni < 4; ni++) {
                const int col = bn + wn0 + ni * 8 + (lane & 3) * 2;
                float2 v;
                v.x = acc[mi][ni][half * 2 + 0];
                v.y = acc[mi][ni][half * 2 + 1];
                *reinterpret_cast<float2*>(C + (size_t)row * N + col) = v;
            }
        }
    }
}

// ---------------- fp32 -> bf16 hi/lo split (elementwise) ----------------
__global__ void split2(const float* __restrict__ x, __nv_bfloat16* __restrict__ h,
                       __nv_bfloat16* __restrict__ l, size_t n)
{
    const size_t stride = (size_t)gridDim.x * blockDim.x * 4;
    for (size_t j = ((size_t)blockIdx.x * blockDim.x + threadIdx.x) * 4; j < n; j += stride) {
        float4 v = *reinterpret_cast<const float4*>(x + j);
        __nv_bfloat16 h0 = __float2bfloat16(v.x), h1 = __float2bfloat16(v.y);
        __nv_bfloat16 h2 = __float2bfloat16(v.z), h3 = __float2bfloat16(v.w);
        __nv_bfloat16 l0 = __float2bfloat16(v.x - __bfloat162float(h0));
        __nv_bfloat16 l1 = __float2bfloat16(v.y - __bfloat162float(h1));
        __nv_bfloat16 l2 = __float2bfloat16(v.z - __bfloat162float(h2));
        __nv_bfloat16 l3 = __float2bfloat16(v.w - __bfloat162float(h3));
        *reinterpret_cast<__nv_bfloat162*>(h + j)     = __halves2bfloat162(h0, h1);
        *reinterpret_cast<__nv_bfloat162*>(h + j + 2) = __halves2bfloat162(h2, h3);
        *reinterpret_cast<__nv_bfloat162*>(l + j)     = __halves2bfloat162(l0, l1);
        *reinterpret_cast<__nv_bfloat162*>(l + j + 2) = __halves2bfloat162(l2, l3);
    }
}

// ---------------- transpose to fp16: knowl [R,Cc] -> vh [Cc,R] ----------------
__global__ void tcvt_f16(const float* __restrict__ in, __half* __restrict__ oh,
                         int R, int Cc)
{
    __shared__ float t[32][33];
    const int c0 = blockIdx.x * 32, r0 = blockIdx.y * 32;
    const int tx = threadIdx.x, ty = threadIdx.y;
#pragma unroll
    for (int j = 0; j < 4; j++)
        t[ty + j * 8][tx] = in[(size_t)(r0 + ty + j * 8) * Cc + c0 + tx];
    __syncthreads();
#pragma unroll
    for (int j = 0; j < 4; j++) {
        const float v = t[tx][ty + j * 8];
        oh[(size_t)(c0 + ty + j * 8) * R + r0 + tx] = __float2half(v);
    }
}

// ---------------- column softmax (axis=0) on row-major [NS, NKK] ----------------
__global__ void col_pmax(const float* __restrict__ scores, float* __restrict__ pmax)
{
    const int col = blockIdx.x * blockDim.x + threadIdx.x;
    const int r0  = blockIdx.y * 256;
    float m = -3.4e38f;
#pragma unroll 16
    for (int r = 0; r < 256; r++)
        m = fmaxf(m, scores[(size_t)(r0 + r) * NKK + col]);
    pmax[blockIdx.y * NKK + col] = m;
}

__global__ void col_max_reduce(const float* __restrict__ pmax, float* __restrict__ cmax)
{
    const int col = blockIdx.x * blockDim.x + threadIdx.x;
    float m = -3.4e38f;
#pragma unroll
    for (int rc = 0; rc < 32; rc++) m = fmaxf(m, pmax[rc * NKK + col]);
    cmax[col] = m;
}

__global__ void col_psum(const float* __restrict__ scores,
                         const float* __restrict__ cmax, float* __restrict__ psum)
{
    const int col = blockIdx.x * blockDim.x + threadIdx.x;
    const int r0  = blockIdx.y * 256;
    const float mx = cmax[col];
    float s = 0.0f;
#pragma unroll 16
    for (int r = 0; r < 256; r++)
        s += __expf(scores[(size_t)(r0 + r) * NKK + col] - mx);
    psum[blockIdx.y * NKK + col] = s;
}

__global__ void col_sum_reduce(const float* __restrict__ psum, float* __restrict__ crcp)
{
    const int col = blockIdx.x * blockDim.x + threadIdx.x;
    float s = 0.0f;
#pragma unroll
    for (int rc = 0; rc < 32; rc++) s += psum[rc * NKK + col];
    crcp[col] = 1.0f / s;
}

// pass 2: attns = exp(score-max)*rcp in place, fused fp16 hi/lo split output
__global__ void softmax_write_split(float* __restrict__ attns,
                                    const float* __restrict__ cmax,
                                    const float* __restrict__ crcp,
                                    __half* __restrict__ ah,
                                    __half* __restrict__ al)
{
    const int col = blockIdx.x * blockDim.x + threadIdx.x;
    const int r0  = blockIdx.y * 32;
    const float mx = cmax[col];
    const float rc = crcp[col];
#pragma unroll
    for (int r = 0; r < 32; r++) {
        const size_t idx = (size_t)(r0 + r) * NKK + col;
        const float v = __expf(attns[idx] - mx) * rc;
        attns[idx] = v;
        const __half h = __float2half(v);
        ah[idx] = h;
        al[idx] = __float2half(v - __half2float(h));
    }
}

// ---------------- launch ----------------
extern "C" void kernel_launch(void* const* d_in, const int* in_sizes, int n_in,
                              void* d_out, int out_size)
{
    (void)in_sizes; (void)n_in; (void)out_size;
    const float* sent  = (const float*)d_in[0];   // [8192, 1024]
    const float* knowl = (const float*)d_in[1];   // [8192, 2048]
    const float* Ws    = (const float*)d_in[2];   // [1024, 1024]
    const float* bs    = (const float*)d_in[3];   // [1024]
    const float* Wk    = (const float*)d_in[4];   // [1024, 2048]
    const float* bk    = (const float*)d_in[5];   // [1024]

    float* attns = (float*)d_out;
    float* fused = attns + (size_t)NS * NKK;

    __nv_bfloat16 *sh, *sl, *wsh, *wsl, *wkh, *wkl, *knh, *knl;
    __nv_bfloat16 *Shp, *Slp, *Khp, *Klp;
    __half *vh, *Ahp, *Alp;
    float *pbuf, *cmaxp, *crcpp;
    cudaGetSymbolAddress((void**)&sh,  g_sh);  cudaGetSymbolAddress((void**)&sl,  g_sl);
    cudaGetSymbolAddress((void**)&wsh, g_wsh); cudaGetSymbolAddress((void**)&wsl, g_wsl);
    cudaGetSymbolAddress((void**)&wkh, g_wkh); cudaGetSymbolAddress((void**)&wkl, g_wkl);
    cudaGetSymbolAddress((void**)&knh, g_knh); cudaGetSymbolAddress((void**)&knl, g_knl);
    cudaGetSymbolAddress((void**)&vh,  g_vh);
    cudaGetSymbolAddress((void**)&Shp, g_Sh);  cudaGetSymbolAddress((void**)&Slp, g_Sl);
    cudaGetSymbolAddress((void**)&Khp, g_Kh);  cudaGetSymbolAddress((void**)&Klp, g_Kl);
    cudaGetSymbolAddress((void**)&Ahp, g_Ah);  cudaGetSymbolAddress((void**)&Alp, g_Al);
    cudaGetSymbolAddress((void**)&pbuf,  g_pbuf);
    cudaGetSymbolAddress((void**)&cmaxp, g_cmax);
    cudaGetSymbolAddress((void**)&crcpp, g_crcp);

    cudaFuncSetAttribute(mma_nt<false>, cudaFuncAttributeMaxDynamicSharedMemorySize, SMEM_BF16);
    cudaFuncSetAttribute(mma_nt<true>,  cudaFuncAttributeMaxDynamicSharedMemorySize, SMEM_BF16);
    cudaFuncSetAttribute(mma_nt_f16,    cudaFuncAttributeMaxDynamicSharedMemorySize, SMEM_F16);

    // 0) split fp32 operands into bf16 hi/lo; V^T to fp16
    split2<<<1184, 256>>>(sent,  sh,  sl,  (size_t)NS * HID);
    split2<<<512,  256>>>(Ws,    wsh, wsl, (size_t)HID * HID);
    split2<<<1024, 256>>>(Wk,    wkh, wkl, (size_t)HID * D2);
    split2<<<1184, 256>>>(knowl, knh, knl, (size_t)NKK * D2);
    tcvt_f16<<<dim3(D2 / 32, NKK / 32), dim3(32, 8)>>>(knowl, vh, NKK, D2);

    // 1) S = sent @ Ws^T + bs  -> split directly to Sh/Sl
    mma_nt<true><<<dim3(HID / 128, NS / 128), 256, SMEM_BF16>>>(
        sh, sl, wsh, wsl, bs, nullptr, Shp, Slp, HID, HID);

    // 2) K = knowl @ Wk^T + bk -> split directly to Kh/Kl
    mma_nt<true><<<dim3(HID / 128, NKK / 128), 256, SMEM_BF16>>>(
        knh, knl, wkh, wkl, bk, nullptr, Khp, Klp, HID, D2);

    // 3) scores = S @ K^T -> attns (fp32)
    mma_nt<false><<<dim3(NKK / 128, NS / 128), 256, SMEM_BF16>>>(
        Shp, Slp, Khp, Klp, nullptr, attns, nullptr, nullptr, NKK, HID);

    // 4) column softmax (axis=0), fused fp16 split of attns into Ah/Al
    col_pmax          <<<dim3(NKK / 256, 32), 256>>>(attns, pbuf);
    col_max_reduce    <<<NKK / 256, 256>>>(pbuf, cmaxp);
    col_psum          <<<dim3(NKK / 256, 32), 256>>>(attns, cmaxp, pbuf);
    col_sum_reduce    <<<NKK / 256, 256>>>(pbuf, crcpp);
    softmax_write_split<<<dim3(NKK / 256, NS / 32), 256>>>(attns, cmaxp, crcpp, Ahp, Alp);

    // 5) fused = (Ah+Al) @ Vh^T   (fp16, 2 products)
    mma_nt_f16<<<dim3(D2 / 128, NS / 128), 256, SMEM_F16>>>(
        Ahp, Alp, vh, fused, D2, NKK);
}